// round 11
// baseline (speedup 1.0000x reference)
#include <cuda_runtime.h>

#define BB 8
#define CC 64
#define NN 400
#define NN2 (NN * NN)          // 160000
#define NV4 (NN / 4)           // 100
#define TT 16                  // tile dim (400 = 25*16 exact)
#define NT 25                  // tiles per dim
#define NPAIR 300              // off-diagonal unordered pairs r<s
#define PPB (NPAIR + NT)       // 325 blocks per batch
#define KT 32                  // k-tile width in epilogue
#define T2LD 516               // padded n-stride (floats) for staged tile

// Scratch (device globals: no allocation allowed in kernel_launch)
__device__ float g_xp[NT * BB * CC * NN];  // partial x by source n-tile (20.5 MB)
__device__ float g_x [BB * CC * NN];       // reduced x                  (0.82 MB)

// ---------------------------------------------------------------------------
// kfused4: one block owns tile pair (r,s)+(s,r). Single DRAM read target.
//   1a: load (r,s): channel max (shuffle-reduced) + stage ch 0..31 in smem.
//   1b: load (s,r): channel max only.
//   2b: acc (s,r) via L2 re-read (hot) using apub1.
//   2a: acc (r,s): ch 0..31 from smem, ch 32..63 via memory, using apub2.
// smem 35 KB -> 6 CTAs/SM kept. No cluster, 1 __syncthreads total.
// ---------------------------------------------------------------------------
__device__ __forceinline__ float relutanh(float m) {
    return (m > 0.f) ? tanhf(m) : 0.f;
}

// max pass over tile (rowt, colt); chain = tid&3 handles 16 channels.
// If STAGE, chains 0,1 also store their channels (0..31) into T2.
template <bool STAGE>
__device__ __forceinline__ void max_pass(const float* __restrict__ R, int b,
                                         int rowt, int colt,
                                         float* __restrict__ T2,
                                         float* __restrict__ apub, int tid) {
    const int chain = tid & 3;
    const int pos   = tid >> 2;           // 0..63
    const int nl    = pos >> 2;           // local row 0..15
    const int k4    = pos & 3;            // col quad 0..3

    const float* base = R + (size_t)(b * CC + chain * 16) * NN2
                          + (size_t)(rowt * TT + nl) * NN + colt * TT + k4 * 4;
    float* t2p = T2 + nl * T2LD + chain * 16 * 16 + k4 * 4;   // c = chain*16+ci

    float4 mx = *reinterpret_cast<const float4*>(base);
    if (STAGE && chain < 2)
        *reinterpret_cast<float4*>(t2p) = mx;
    #pragma unroll
    for (int ci = 1; ci < 16; ++ci) {
        float4 v = *reinterpret_cast<const float4*>(base + (size_t)ci * NN2);
        if (STAGE && chain < 2)
            *reinterpret_cast<float4*>(t2p + ci * 16) = v;
        mx.x = fmaxf(mx.x, v.x); mx.y = fmaxf(mx.y, v.y);
        mx.z = fmaxf(mx.z, v.z); mx.w = fmaxf(mx.w, v.w);
    }
    // combine 4 chains (lanes tid^1, tid^2 within the quad)
    mx.x = fmaxf(mx.x, __shfl_xor_sync(0xffffffffu, mx.x, 1));
    mx.y = fmaxf(mx.y, __shfl_xor_sync(0xffffffffu, mx.y, 1));
    mx.z = fmaxf(mx.z, __shfl_xor_sync(0xffffffffu, mx.z, 1));
    mx.w = fmaxf(mx.w, __shfl_xor_sync(0xffffffffu, mx.w, 1));
    mx.x = fmaxf(mx.x, __shfl_xor_sync(0xffffffffu, mx.x, 2));
    mx.y = fmaxf(mx.y, __shfl_xor_sync(0xffffffffu, mx.y, 2));
    mx.z = fmaxf(mx.z, __shfl_xor_sync(0xffffffffu, mx.z, 2));
    mx.w = fmaxf(mx.w, __shfl_xor_sync(0xffffffffu, mx.w, 2));

    if (chain == 0) {                     // one lane per position publishes
        int jq = k4 * 4;
        apub[(jq + 0) * TT + nl] = relutanh(mx.x);
        apub[(jq + 1) * TT + nl] = relutanh(mx.y);
        apub[(jq + 2) * TT + nl] = relutanh(mx.z);
        apub[(jq + 3) * TT + nl] = relutanh(mx.w);
    }
}

// acc via global re-read only (used for the hot tile (s,r)).
__device__ __forceinline__ void acc_gmem(const float* __restrict__ R, int b,
                                         int rt, int ct,
                                         const float* __restrict__ a, int tid) {
    const int c  = tid >> 2;
    const int kg = (tid & 3) * 4;
    const float* rb = R + (size_t)(b * CC + c) * NN2
                        + (size_t)(rt * TT) * NN + ct * TT + kg;
    float4 acc = make_float4(0.f, 0.f, 0.f, 0.f);
    #pragma unroll
    for (int n = 0; n < TT; ++n) {
        float4 r  = *reinterpret_cast<const float4*>(rb + (size_t)n * NN);
        float4 av = *reinterpret_cast<const float4*>(a + n * TT + kg);
        acc.x = fmaf(r.x, av.x, acc.x);
        acc.y = fmaf(r.y, av.y, acc.y);
        acc.z = fmaf(r.z, av.z, acc.z);
        acc.w = fmaf(r.w, av.w, acc.w);
    }
    *reinterpret_cast<float4*>(
        g_xp + (((size_t)rt * BB + b) * CC + c) * NN + ct * TT + kg) = acc;
}

// acc for the staged tile: warps 0-3 (c<32) read smem, warps 4-7 read memory.
__device__ __forceinline__ void acc_mixed(const float* __restrict__ R, int b,
                                          int rt, int ct,
                                          const float* __restrict__ T2,
                                          const float* __restrict__ a, int tid) {
    const int c  = tid >> 2;
    const int kg = (tid & 3) * 4;
    float4 acc = make_float4(0.f, 0.f, 0.f, 0.f);
    if (c < 32) {
        const float* t2p = T2 + c * 16 + kg;
        #pragma unroll
        for (int n = 0; n < TT; ++n) {
            float4 r  = *reinterpret_cast<const float4*>(t2p + n * T2LD);
            float4 av = *reinterpret_cast<const float4*>(a + n * TT + kg);
            acc.x = fmaf(r.x, av.x, acc.x);
            acc.y = fmaf(r.y, av.y, acc.y);
            acc.z = fmaf(r.z, av.z, acc.z);
            acc.w = fmaf(r.w, av.w, acc.w);
        }
    } else {
        const float* rb = R + (size_t)(b * CC + c) * NN2
                            + (size_t)(rt * TT) * NN + ct * TT + kg;
        #pragma unroll
        for (int n = 0; n < TT; ++n) {
            float4 r  = *reinterpret_cast<const float4*>(rb + (size_t)n * NN);
            float4 av = *reinterpret_cast<const float4*>(a + n * TT + kg);
            acc.x = fmaf(r.x, av.x, acc.x);
            acc.y = fmaf(r.y, av.y, acc.y);
            acc.z = fmaf(r.z, av.z, acc.z);
            acc.w = fmaf(r.w, av.w, acc.w);
        }
    }
    *reinterpret_cast<float4*>(
        g_xp + (((size_t)rt * BB + b) * CC + c) * NN + ct * TT + kg) = acc;
}

__global__ void __launch_bounds__(256, 6) kfused4(const float* __restrict__ R) {
    __shared__ float T2[TT * T2LD];       // staged (r,s) ch 0..31: 33024 B
    __shared__ float apub1[TT * TT];      // f-tile of (r,s): 1 KB
    __shared__ float apub2[TT * TT];      // f-tile of (s,r): 1 KB

    const int idx   = blockIdx.x;
    const int b     = idx / PPB;
    const int local = idx - b * PPB;
    const int tid   = threadIdx.x;

    if (local < NPAIR) {
        int r = 0, rem = local;
        while (rem >= (NT - 1) - r) { rem -= (NT - 1) - r; ++r; }
        int s = r + 1 + rem;

        max_pass<true >(R, b, r, s, T2, apub1, tid);  // stage (r,s) ch 0..31
        max_pass<false>(R, b, s, r, T2, apub2, tid);
        __syncthreads();                              // apubs + T2 visible
        acc_gmem (R, b, s, r, apub1, tid);            // (s,r) L2-hot
        acc_mixed(R, b, r, s, T2, apub2, tid);        // (r,s): smem + cold half
    } else {
        int d = local - NPAIR;                        // diagonal tile
        max_pass<true>(R, b, d, d, T2, apub1, tid);
        __syncthreads();
        acc_mixed(R, b, d, d, T2, apub1, tid);        // all hot/smem
    }
}

// ---------------------------------------------------------------------------
// k3a (R9 verbatim): g_x = sum over 25 slots of g_xp.
// ---------------------------------------------------------------------------
__global__ void k3a_reduce() {
    const int total4 = BB * CC * NV4;                  // 51200
    int t = blockIdx.x * blockDim.x + threadIdx.x;
    if (t >= total4) return;
    const float4* xp4 = reinterpret_cast<const float4*>(g_xp);
    const int stride4 = BB * CC * NV4;

    float4 s0 = xp4[t];
    float4 s1 = xp4[(size_t)1 * stride4 + t];
    float4 s2 = xp4[(size_t)2 * stride4 + t];
    float4 s3 = xp4[(size_t)3 * stride4 + t];
    #pragma unroll
    for (int slot = 4; slot + 3 < NT; slot += 4) {
        float4 v0 = xp4[(size_t)(slot + 0) * stride4 + t];
        float4 v1 = xp4[(size_t)(slot + 1) * stride4 + t];
        float4 v2 = xp4[(size_t)(slot + 2) * stride4 + t];
        float4 v3 = xp4[(size_t)(slot + 3) * stride4 + t];
        s0.x += v0.x; s0.y += v0.y; s0.z += v0.z; s0.w += v0.w;
        s1.x += v1.x; s1.y += v1.y; s1.z += v1.z; s1.w += v1.w;
        s2.x += v2.x; s2.y += v2.y; s2.z += v2.z; s2.w += v2.w;
        s3.x += v3.x; s3.y += v3.y; s3.z += v3.z; s3.w += v3.w;
    }
    {
        float4 v = xp4[(size_t)24 * stride4 + t];
        s0.x += v.x; s0.y += v.y; s0.z += v.z; s0.w += v.w;
    }
    float4 s;
    s.x = (s0.x + s1.x) + (s2.x + s3.x);
    s.y = (s0.y + s1.y) + (s2.y + s3.y);
    s.z = (s0.z + s1.z) + (s2.z + s3.z);
    s.w = (s0.w + s1.w) + (s2.w + s3.w);
    reinterpret_cast<float4*>(g_x)[t] = s;
}

// ---------------------------------------------------------------------------
// k3b (R4 verbatim): out[b,o,k] = sum_c W[o,c] * x[b,c,k] + bias[o]
// ---------------------------------------------------------------------------
__global__ void k3b_linear(const float* __restrict__ W,
                           const float* __restrict__ bias,
                           float* __restrict__ out) {
    __shared__ float xs[CC][KT + 1];
    const int b  = blockIdx.z;
    const int og = blockIdx.y;
    const int k0 = blockIdx.x * KT;
    const int x  = threadIdx.x;
    const int y  = threadIdx.y;
    const int k  = k0 + x;
    const bool valid = (k < NN);
    const int kc = valid ? k : (NN - 1);

    for (int c = y; c < CC; c += 8)
        xs[c][x] = g_x[((size_t)b * CC + c) * NN + kc];
    __syncthreads();

    #pragma unroll
    for (int oi = 0; oi < 2; ++oi) {
        int o = og * 16 + y + oi * 8;
        float acc = bias[o];
        const float* wr = W + o * CC;
        #pragma unroll 16
        for (int c = 0; c < CC; ++c)
            acc = fmaf(wr[c], xs[c][x], acc);
        if (valid)
            out[((size_t)b * CC + o) * NN + k] = acc;
    }
}

// ---------------------------------------------------------------------------
extern "C" void kernel_launch(void* const* d_in, const int* in_sizes, int n_in,
                              void* d_out, int out_size) {
    const float* R    = (const float*)d_in[0];
    const float* W    = (const float*)d_in[1];
    const float* bias = (const float*)d_in[2];
    float*       out  = (float*)d_out;

    // Fused single-read kernel: 8 * 325 = 2600 plain blocks
    kfused4<<<BB * PPB, 256>>>(R);

    // k3a: 25-slot partial reduce (200 blocks)
    {
        int total4 = BB * CC * NV4;
        k3a_reduce<<<(total4 + 255) / 256, 256>>>();
    }

    // k3b: linear (416 blocks)
    {
        dim3 grid((NN + KT - 1) / KT, 4, BB);
        dim3 blk(32, 8);
        k3b_linear<<<grid, blk>>>(W, bias, out);
    }
}

// round 12
// speedup vs baseline: 1.9105x; 1.9105x over previous
#include <cuda_runtime.h>
#include <cooperative_groups.h>
namespace cg = cooperative_groups;

#define BB 8
#define CC 64
#define NN 400
#define NN2 (NN * NN)          // 160000
#define NV4 (NN / 4)           // 100
#define TT 16                  // tile dim (400 = 25*16 exact)
#define NT 25                  // tiles per dim
#define NPAIR 300              // off-diagonal unordered pairs r<s
#define NDIAGC 13              // diagonal clusters (12 full + 1 half)
#define CLPB (NPAIR + NDIAGC)  // 313 clusters per batch
#define KT 32                  // k-tile width in epilogue

// Scratch (device globals: no allocation allowed in kernel_launch)
__device__ float g_xp[NT * BB * CC * NN];  // partial x by source n-tile (20.5 MB)
__device__ float g_x [BB * CC * NN];       // reduced x                  (0.82 MB)

// ---------------------------------------------------------------------------
// kfused5 = R9's kfused2 (measured 85.6us, ~405MB DRAM) with ONE change:
// the f-tile is written DIRECTLY into the partner's atp via DSMEM
// (map_shared_rank store), and the two cluster.sync()s collapse to one.
// After the single sync each CTA reads only LOCAL smem, so partner exit
// is safe. Load layout/phases are untouched (R11 lesson).
// ---------------------------------------------------------------------------
__global__ void __launch_bounds__(256, 6) kfused5(const float* __restrict__ R) {
    __shared__ float cm[4 * 64 * 4];      // per-chain maxes (float4 each): 4 KB
    __shared__ float atp[TT * TT];        // f-tile of PARTNER's R-tile:   1 KB

    cg::cluster_group cl = cg::this_cluster();
    const int rank  = (int)cl.block_rank();
    const int cid   = (int)blockIdx.x >> 1;
    const int b     = cid / CLPB;
    const int local = cid - b * CLPB;

    int rt, ct;
    bool active = true;
    bool have_partner;
    if (local < NPAIR) {
        int r = 0, rem = local;
        while (rem >= (NT - 1) - r) { rem -= (NT - 1) - r; ++r; }
        int s = r + 1 + rem;
        rt = rank ? s : r;
        ct = rank ? r : s;
        have_partner = true;
    } else {
        int d  = local - NPAIR;
        int dg = 2 * d + rank;
        active = (dg < NT);
        rt = ct = active ? dg : 0;
        have_partner = false;
    }

    const int tid   = threadIdx.x;        // 256
    const int p     = tid & 63;
    const int chain = tid >> 6;           // 0..3 -> channels chain*16..+15 (warp-coherent)
    const int nl    = p >> 2;             // local row 0..15
    const int k4    = p & 3;              // k quad 0..3

    // ---- Phase 1: channel max over my 16 channels at (nl, k4*4..+3) ----
    if (active) {
        const float* base = R + (size_t)(b * CC + chain * 16) * NN2
                              + (size_t)(rt * TT + nl) * NN + ct * TT + k4 * 4;
        float4 mx = *reinterpret_cast<const float4*>(base);
        #pragma unroll
        for (int ci = 1; ci < 16; ++ci) {
            float4 v = *reinterpret_cast<const float4*>(base + (size_t)ci * NN2);
            mx.x = fmaxf(mx.x, v.x); mx.y = fmaxf(mx.y, v.y);
            mx.z = fmaxf(mx.z, v.z); mx.w = fmaxf(mx.w, v.w);
        }
        *reinterpret_cast<float4*>(cm + (chain * 64 + p) * 4) = mx;
    }
    __syncthreads();

    // ---- combine 4 chains, relu(tanh), write TRANSPOSED f-tile directly
    //      into the PARTNER's atp (remote DSMEM store; local for diagonal) ----
    if (active && tid < 64) {
        float4 m0 = *reinterpret_cast<float4*>(cm + (0 * 64 + tid) * 4);
        float4 m1 = *reinterpret_cast<float4*>(cm + (1 * 64 + tid) * 4);
        float4 m2 = *reinterpret_cast<float4*>(cm + (2 * 64 + tid) * 4);
        float4 m3 = *reinterpret_cast<float4*>(cm + (3 * 64 + tid) * 4);
        float4 m;
        m.x = fmaxf(fmaxf(m0.x, m1.x), fmaxf(m2.x, m3.x));
        m.y = fmaxf(fmaxf(m0.y, m1.y), fmaxf(m2.y, m3.y));
        m.z = fmaxf(fmaxf(m0.z, m1.z), fmaxf(m2.z, m3.z));
        m.w = fmaxf(fmaxf(m0.w, m1.w), fmaxf(m2.w, m3.w));
        int i  = tid >> 2;                // local row of MY tile
        int jq = (tid & 3) * 4;           // local col quad of MY tile
        float* dst = atp;
        if (have_partner)
            dst = (float*)cl.map_shared_rank((void*)atp, rank ^ 1);
        dst[(jq + 0) * TT + i] = (m.x > 0.f) ? tanhf(m.x) : 0.f;
        dst[(jq + 1) * TT + i] = (m.y > 0.f) ? tanhf(m.y) : 0.f;
        dst[(jq + 2) * TT + i] = (m.z > 0.f) ? tanhf(m.z) : 0.f;
        dst[(jq + 3) * TT + i] = (m.w > 0.f) ? tanhf(m.w) : 0.f;
    }

    // ---- single rendezvous: partner's writes into my atp are ordered
    //      before the barrier release; afterwards everything is local ----
    cl.sync();

    // ---- Phase 2: re-read own tile (L2-hot), accumulate ----
    // atp[n][k_local] = A[b, ct*16+k, rt*16+n]  (written by partner)
    if (active) {
        const int c  = tid >> 2;          // 0..63
        const int kg = (tid & 3) * 4;     // k quad base
        const float* rb = R + (size_t)(b * CC + c) * NN2
                            + (size_t)(rt * TT) * NN + ct * TT + kg;
        float4 acc = make_float4(0.f, 0.f, 0.f, 0.f);
        #pragma unroll 8
        for (int n = 0; n < TT; ++n) {
            float4 r = *reinterpret_cast<const float4*>(rb + (size_t)n * NN);
            float4 a = *reinterpret_cast<const float4*>(atp + n * TT + kg);
            acc.x = fmaf(r.x, a.x, acc.x);
            acc.y = fmaf(r.y, a.y, acc.y);
            acc.z = fmaf(r.z, a.z, acc.z);
            acc.w = fmaf(r.w, a.w, acc.w);
        }
        *reinterpret_cast<float4*>(
            g_xp + (((size_t)rt * BB + b) * CC + c) * NN + ct * TT + kg) = acc;
    }
}

// ---------------------------------------------------------------------------
// k3a (R9 verbatim): g_x = sum over 25 slots of g_xp.
// ---------------------------------------------------------------------------
__global__ void k3a_reduce() {
    const int total4 = BB * CC * NV4;                  // 51200
    int t = blockIdx.x * blockDim.x + threadIdx.x;
    if (t >= total4) return;
    const float4* xp4 = reinterpret_cast<const float4*>(g_xp);
    const int stride4 = BB * CC * NV4;

    float4 s0 = xp4[t];
    float4 s1 = xp4[(size_t)1 * stride4 + t];
    float4 s2 = xp4[(size_t)2 * stride4 + t];
    float4 s3 = xp4[(size_t)3 * stride4 + t];
    #pragma unroll
    for (int slot = 4; slot + 3 < NT; slot += 4) {
        float4 v0 = xp4[(size_t)(slot + 0) * stride4 + t];
        float4 v1 = xp4[(size_t)(slot + 1) * stride4 + t];
        float4 v2 = xp4[(size_t)(slot + 2) * stride4 + t];
        float4 v3 = xp4[(size_t)(slot + 3) * stride4 + t];
        s0.x += v0.x; s0.y += v0.y; s0.z += v0.z; s0.w += v0.w;
        s1.x += v1.x; s1.y += v1.y; s1.z += v1.z; s1.w += v1.w;
        s2.x += v2.x; s2.y += v2.y; s2.z += v2.z; s2.w += v2.w;
        s3.x += v3.x; s3.y += v3.y; s3.z += v3.z; s3.w += v3.w;
    }
    {
        float4 v = xp4[(size_t)24 * stride4 + t];
        s0.x += v.x; s0.y += v.y; s0.z += v.z; s0.w += v.w;
    }
    float4 s;
    s.x = (s0.x + s1.x) + (s2.x + s3.x);
    s.y = (s0.y + s1.y) + (s2.y + s3.y);
    s.z = (s0.z + s1.z) + (s2.z + s3.z);
    s.w = (s0.w + s1.w) + (s2.w + s3.w);
    reinterpret_cast<float4*>(g_x)[t] = s;
}

// ---------------------------------------------------------------------------
// k3b (R4 verbatim): out[b,o,k] = sum_c W[o,c] * x[b,c,k] + bias[o]
// ---------------------------------------------------------------------------
__global__ void k3b_linear(const float* __restrict__ W,
                           const float* __restrict__ bias,
                           float* __restrict__ out) {
    __shared__ float xs[CC][KT + 1];
    const int b  = blockIdx.z;
    const int og = blockIdx.y;
    const int k0 = blockIdx.x * KT;
    const int x  = threadIdx.x;
    const int y  = threadIdx.y;
    const int k  = k0 + x;
    const bool valid = (k < NN);
    const int kc = valid ? k : (NN - 1);

    for (int c = y; c < CC; c += 8)
        xs[c][x] = g_x[((size_t)b * CC + c) * NN + kc];
    __syncthreads();

    #pragma unroll
    for (int oi = 0; oi < 2; ++oi) {
        int o = og * 16 + y + oi * 8;
        float acc = bias[o];
        const float* wr = W + o * CC;
        #pragma unroll 16
        for (int c = 0; c < CC; ++c)
            acc = fmaf(wr[c], xs[c][x], acc);
        if (valid)
            out[((size_t)b * CC + o) * NN + k] = acc;
    }
}

// ---------------------------------------------------------------------------
extern "C" void kernel_launch(void* const* d_in, const int* in_sizes, int n_in,
                              void* d_out, int out_size) {
    const float* R    = (const float*)d_in[0];
    const float* W    = (const float*)d_in[1];
    const float* bias = (const float*)d_in[2];
    float*       out  = (float*)d_out;

    // Fused single-read kernel: 8 * 313 clusters * 2 CTAs = 5008 blocks
    {
        cudaLaunchConfig_t cfg = {};
        cfg.gridDim  = dim3(BB * CLPB * 2, 1, 1);
        cfg.blockDim = dim3(256, 1, 1);
        cfg.dynamicSmemBytes = 0;
        cfg.stream = 0;
        cudaLaunchAttribute attrs[1];
        attrs[0].id = cudaLaunchAttributeClusterDimension;
        attrs[0].val.clusterDim = {2, 1, 1};
        cfg.attrs = attrs;
        cfg.numAttrs = 1;
        cudaLaunchKernelEx(&cfg, kfused5, R);
    }

    // k3a: 25-slot partial reduce (200 blocks)
    {
        int total4 = BB * CC * NV4;
        k3a_reduce<<<(total4 + 255) / 256, 256>>>();
    }

    // k3b: linear (416 blocks)
    {
        dim3 grid((NN + KT - 1) / KT, 4, BB);
        dim3 blk(32, 8);
        k3b_linear<<<grid, blk>>>(W, bias, out);
    }
}